// round 5
// baseline (speedup 1.0000x reference)
#include <cuda_runtime.h>
#include <math.h>
#include <stdint.h>

// Problem constants
#define BATCH 2
#define SEQ   2048
#define DMODEL 1024
#define NHEAD 16
#define DHEAD 64
#define MTOT  (BATCH*SEQ)      // 4096
#define LAMBDA_INIT 0.8f
#define LN_EPS 1e-5f

// ---------------------------------------------------------------------------
// Scratch
// ---------------------------------------------------------------------------
__device__ float g_q0[MTOT*DMODEL];
__device__ float g_q1[MTOT*DMODEL];
__device__ float g_k0[MTOT*DMODEL];
__device__ float g_k1[MTOT*DMODEL];
__device__ float g_v [MTOT*DMODEL];
__device__ float g_attn[MTOT*DMODEL];
__device__ float g_lambda;

__device__ __forceinline__ uint32_t cvt_tf32(float x) {
    uint32_t r;
    asm("cvt.rna.tf32.f32 %0, %1;" : "=r"(r) : "f"(x));
    return r;
}
__device__ __forceinline__ float tf32f(float x) {
    return __uint_as_float(cvt_tf32(x));
}

// ---------------------------------------------------------------------------
// Lambda scalar
// ---------------------------------------------------------------------------
__global__ void lambda_kernel(const float* __restrict__ l0, const float* __restrict__ l1,
                              const float* __restrict__ l2, const float* __restrict__ l3) {
    int t = threadIdx.x; // 32 threads
    float a = l0[t]*l1[t] + l0[t+32]*l1[t+32];
    float b = l2[t]*l3[t] + l2[t+32]*l3[t+32];
    #pragma unroll
    for (int o = 16; o >= 1; o >>= 1) {
        a += __shfl_xor_sync(0xffffffffu, a, o);
        b += __shfl_xor_sync(0xffffffffu, b, o);
    }
    if (t == 0) g_lambda = (-expf(a) + LAMBDA_INIT) + (-expf(b) + LAMBDA_INIT);
}

// ---------------------------------------------------------------------------
// TF32 tensor-core GEMM body (shared by single and batched-projection kernels)
// 128x128x32 block tile, 256 threads, mma.m16n8k8.tf32, cp.async dbl-buffered.
// ---------------------------------------------------------------------------
#define BM 128
#define BN 128
#define BK 32
#define A_LD 36
#define B_LD 136
#define AS_STAGE (BM*A_LD)
#define BS_STAGE (BK*B_LD)
#define GEMM_SMEM_BYTES ((2*(AS_STAGE+BS_STAGE))*4)

__device__ __forceinline__ void gemm_body(const float* __restrict__ A,
                                          const float* __restrict__ B,
                                          float* __restrict__ C,
                                          int M, int N, int K) {
    extern __shared__ float sm[];
    float* As = sm;
    float* Bs = sm + 2 * AS_STAGE;

    int tid  = threadIdx.x;
    int lane = tid & 31;
    int warp = tid >> 5;
    int g    = lane >> 2;
    int tig  = lane & 3;
    int wm   = (warp >> 2) * 64;
    int wn   = (warp & 3) * 32;

    int bx = blockIdx.x, by = blockIdx.y;

    const float* Ag = A + (size_t)(by * BM) * K;
    const float* Bg = B + bx * BN;

    int a_row = tid >> 3;
    int a_col = (tid & 7) * 4;
    int b_row = tid >> 5;
    int b_col = (tid & 31) * 4;

    uint32_t s_as = (uint32_t)__cvta_generic_to_shared(As);
    uint32_t s_bs = (uint32_t)__cvta_generic_to_shared(Bs);

    float acc[4][4][4];
    #pragma unroll
    for (int i = 0; i < 4; i++)
        #pragma unroll
        for (int j = 0; j < 4; j++)
            #pragma unroll
            for (int q = 0; q < 4; q++) acc[i][j][q] = 0.f;

    uint32_t a_lane_off = ((uint32_t)((wm + (lane & 15)) * A_LD + (lane >> 4) * 4)) * 4u;

    const int NT = K / BK;

    auto prefetch = [&](int kt, int stage) {
        uint32_t ad = s_as + (uint32_t)stage * AS_STAGE * 4;
        const float* ag = Ag + kt * BK;
        #pragma unroll
        for (int r = 0; r < 4; r++) {
            int row = a_row + r * 32;
            uint32_t dst = ad + (uint32_t)(row * A_LD + a_col) * 4;
            const float* src = ag + (size_t)row * K + a_col;
            asm volatile("cp.async.cg.shared.global [%0], [%1], 16;\n" :: "r"(dst), "l"(src));
        }
        uint32_t bd = s_bs + (uint32_t)stage * BS_STAGE * 4;
        const float* bg = Bg + (size_t)(kt * BK) * N;
        #pragma unroll
        for (int r = 0; r < 4; r++) {
            int row = b_row + r * 8;
            uint32_t dst = bd + (uint32_t)(row * B_LD + b_col) * 4;
            const float* src = bg + (size_t)row * N + b_col;
            asm volatile("cp.async.cg.shared.global [%0], [%1], 16;\n" :: "r"(dst), "l"(src));
        }
        asm volatile("cp.async.commit_group;\n");
    };

    prefetch(0, 0);

    for (int kt = 0; kt < NT; kt++) {
        int stage = kt & 1;
        if (kt + 1 < NT) {
            prefetch(kt + 1, stage ^ 1);
            asm volatile("cp.async.wait_group 1;\n");
        } else {
            asm volatile("cp.async.wait_group 0;\n");
        }
        __syncthreads();

        uint32_t a_base = s_as + (uint32_t)stage * AS_STAGE * 4 + a_lane_off;
        const float* bsp = Bs + stage * BS_STAGE;

        #pragma unroll
        for (int k8 = 0; k8 < BK / 8; k8++) {
            uint32_t arg[4][4];
            #pragma unroll
            for (int i = 0; i < 4; i++) {
                uint32_t addr = a_base + (uint32_t)(i * 16 * A_LD + k8 * 8) * 4;
                asm volatile("ldmatrix.sync.aligned.m8n8.x4.shared.b16 {%0,%1,%2,%3}, [%4];\n"
                             : "=r"(arg[i][0]), "=r"(arg[i][1]), "=r"(arg[i][2]), "=r"(arg[i][3])
                             : "r"(addr));
            }
            uint32_t brg[4][2];
            #pragma unroll
            for (int j = 0; j < 4; j++) {
                float b0 = bsp[(k8 * 8 + tig)     * B_LD + wn + j * 8 + g];
                float b1 = bsp[(k8 * 8 + tig + 4) * B_LD + wn + j * 8 + g];
                brg[j][0] = cvt_tf32(b0);
                brg[j][1] = cvt_tf32(b1);
            }
            #pragma unroll
            for (int i = 0; i < 4; i++)
                #pragma unroll
                for (int q = 0; q < 4; q++)
                    arg[i][q] = cvt_tf32(__uint_as_float(arg[i][q]));

            #pragma unroll
            for (int i = 0; i < 4; i++)
                #pragma unroll
                for (int j = 0; j < 4; j++)
                    asm volatile(
                        "mma.sync.aligned.m16n8k8.row.col.f32.tf32.tf32.f32 "
                        "{%0,%1,%2,%3}, {%4,%5,%6,%7}, {%8,%9}, {%0,%1,%2,%3};\n"
                        : "+f"(acc[i][j][0]), "+f"(acc[i][j][1]),
                          "+f"(acc[i][j][2]), "+f"(acc[i][j][3])
                        : "r"(arg[i][0]), "r"(arg[i][1]), "r"(arg[i][2]), "r"(arg[i][3]),
                          "r"(brg[j][0]), "r"(brg[j][1]));
        }
        __syncthreads();
    }

    #pragma unroll
    for (int i = 0; i < 4; i++) {
        int row = by * BM + wm + i * 16 + g;
        #pragma unroll
        for (int j = 0; j < 4; j++) {
            int col = bx * BN + wn + j * 8 + 2 * tig;
            *(float2*)(C + (size_t)row * N + col)       = make_float2(acc[i][j][0], acc[i][j][1]);
            *(float2*)(C + (size_t)(row + 8) * N + col) = make_float2(acc[i][j][2], acc[i][j][3]);
        }
    }
}

__global__ __launch_bounds__(256, 1) void gemm_tf32(const float* __restrict__ A,
                                                    const float* __restrict__ B,
                                                    float* __restrict__ C,
                                                    int M, int N, int K) {
    gemm_body(A, B, C, M, N, K);
}

// Batched projections: z selects weight/output; all share A (L2 reuse).
struct ProjPtrs { const float* W[5]; float* O[5]; };

__global__ __launch_bounds__(256, 1) void gemm_proj(const float* __restrict__ A,
                                                    ProjPtrs p, int M, int N, int K) {
    gemm_body(A, p.W[blockIdx.z], p.O[blockIdx.z], M, N, K);
}

// ---------------------------------------------------------------------------
// Tensor-core differential flash attention + per-head LayerNorm.
// 128 threads = 4 warps; warp w owns q rows [w*16, w*16+16).
// K kept NATURAL [kv][dh] (mma col-major B frag reads it directly; no transpose).
// Per kt: one vectorized load phase (K0,K1,V) + 2 block syncs total.
// ---------------------------------------------------------------------------
#define QLD 68   // %32=4 -> ldmatrix float-quadrant geometry, conflict-free
#define PLD 68
#define KLD 68   // %32=4 -> QK B-frag scalar LDS conflict-free (g*4+tig)
#define VLD 72   // %32=8 -> PV B-frag scalar LDS conflict-free ((tig+j)*8+g)
#define SQ_OFF  0
#define SK0_OFF (2*64*QLD)              // 8704
#define SK1_OFF (SK0_OFF + 64*KLD)      // 13056
#define SV_OFF  (SK1_OFF + 64*KLD)      // 17408
#define SP_OFF  (SV_OFF + 64*VLD)       // 22016
#define ATTN2_SMEM_FLOATS (SP_OFF + 64*PLD)   // 26368
#define ATTN2_SMEM_BYTES (ATTN2_SMEM_FLOATS*4) // 105472

__global__ __launch_bounds__(128) void attn_tc_kernel(
        const float* __restrict__ q0b, const float* __restrict__ q1b,
        const float* __restrict__ k0b, const float* __restrict__ k1b,
        const float* __restrict__ vb,
        const float* __restrict__ ln_w, const float* __restrict__ ln_b,
        float* __restrict__ attn) {
    extern __shared__ float sm[];
    float* sQ  = sm + SQ_OFF;    // [2][64][QLD] tf32 bits
    float* sK0 = sm + SK0_OFF;   // [64 kv][KLD] natural, tf32 bits
    float* sK1 = sm + SK1_OFF;
    float* sV  = sm + SV_OFF;    // [64 kv][VLD] natural, tf32 bits
    float* sP  = sm + SP_OFF;    // [64 q][PLD] tf32 bits, per-stream reuse

    int qt = gridDim.x - 1 - blockIdx.x;   // heavy tiles first
    int bh = blockIdx.y;
    int b = bh >> 4, h = bh & 15;

    int tid = threadIdx.x;
    int lane = tid & 31;
    int w = tid >> 5;
    int g = lane >> 2;
    int tig = lane & 3;

    const float scale = 0.125f;
    const float slope = exp2f(-0.5f * (float)(h + 1));
    const size_t base = (size_t)b * SEQ * DMODEL + (size_t)h * DHEAD;

    // fill thread mapping: row = tid&63, half = tid>>6
    const int frow = tid & 63;
    const int fc0  = (tid >> 6) * 32;

    // --- load Q (both streams), row-major, pre-cvt tf32 ---
    {
        size_t gofs = base + (size_t)(qt * 64 + frow) * DMODEL + fc0;
        #pragma unroll
        for (int st = 0; st < 2; st++) {
            const float* src = (st == 0) ? q0b : q1b;
            float* dst = sQ + st * 64 * QLD + frow * QLD + fc0;
            #pragma unroll
            for (int c = 0; c < 32; c += 4) {
                float4 v4 = *(const float4*)(src + gofs + c);
                dst[c + 0] = tf32f(v4.x);
                dst[c + 1] = tf32f(v4.y);
                dst[c + 2] = tf32f(v4.z);
                dst[c + 3] = tf32f(v4.w);
            }
        }
    }

    float oacc[2][8][4];
    #pragma unroll
    for (int st = 0; st < 2; st++)
        #pragma unroll
        for (int j = 0; j < 8; j++)
            #pragma unroll
            for (int q = 0; q < 4; q++) oacc[st][j][q] = 0.f;
    float mrow[2][2], lrow[2][2];
    #pragma unroll
    for (int st = 0; st < 2; st++)
        #pragma unroll
        for (int hh = 0; hh < 2; hh++) { mrow[st][hh] = -INFINITY; lrow[st][hh] = 0.f; }

    uint32_t s_q = (uint32_t)__cvta_generic_to_shared(sQ);
    uint32_t s_p = (uint32_t)__cvta_generic_to_shared(sP);
    uint32_t qa_lane = ((uint32_t)((w * 16 + (lane & 15)) * QLD + (lane >> 4) * 4)) * 4u;
    uint32_t pa_lane = s_p + ((uint32_t)((w * 16 + (lane & 15)) * PLD + (lane >> 4) * 4)) * 4u;

    const int qrow0 = qt * 64 + w * 16;
    const int qq0 = qrow0 + g;

    for (int kt = 0; kt <= qt; kt++) {
        const bool diag = (kt == qt);
        // ---- load K0, K1, V tiles (natural layout, vectorized, pre-cvt) ----
        {
            size_t gofs = base + (size_t)(kt * 64 + frow) * DMODEL + fc0;
            const float* gk0 = k0b + gofs;
            const float* gk1 = k1b + gofs;
            const float* gv  = vb  + gofs;
            float* dk0 = sK0 + frow * KLD + fc0;
            float* dk1 = sK1 + frow * KLD + fc0;
            float* dv  = sV  + frow * VLD + fc0;
            #pragma unroll
            for (int c = 0; c < 32; c += 4) {
                float4 a4 = *(const float4*)(gk0 + c);
                dk0[c + 0] = tf32f(a4.x); dk0[c + 1] = tf32f(a4.y);
                dk0[c + 2] = tf32f(a4.z); dk0[c + 3] = tf32f(a4.w);
                float4 b4 = *(const float4*)(gk1 + c);
                dk1[c + 0] = tf32f(b4.x); dk1[c + 1] = tf32f(b4.y);
                dk1[c + 2] = tf32f(b4.z); dk1[c + 3] = tf32f(b4.w);
                float4 c4 = *(const float4*)(gv + c);
                dv[c + 0] = tf32f(c4.x); dv[c + 1] = tf32f(c4.y);
                dv[c + 2] = tf32f(c4.z); dv[c + 3] = tf32f(c4.w);
            }
        }
        __syncthreads();   // tiles ready

        #pragma unroll
        for (int st = 0; st < 2; st++) {
            const float* sK = (st == 0) ? sK0 : sK1;

            // ---- QK: scores [16 q rows x 64 kv] per warp ----
            float sc[8][4];
            #pragma unroll
            for (int j = 0; j < 8; j++)
                #pragma unroll
                for (int q = 0; q < 4; q++) sc[j][q] = 0.f;

            uint32_t qa_base = s_q + (uint32_t)(st * 64 * QLD) * 4u + qa_lane;
            #pragma unroll
            for (int k8 = 0; k8 < 8; k8++) {
                uint32_t a0, a1, a2, a3;
                uint32_t addr = qa_base + (uint32_t)(k8 * 8) * 4u;
                asm volatile("ldmatrix.sync.aligned.m8n8.x4.shared.b16 {%0,%1,%2,%3}, [%4];\n"
                             : "=r"(a0), "=r"(a1), "=r"(a2), "=r"(a3) : "r"(addr));
                #pragma unroll
                for (int j = 0; j < 8; j++) {
                    const float* kr = sK + (j * 8 + g) * KLD + k8 * 8;
                    uint32_t b0 = __float_as_uint(kr[tig]);
                    uint32_t b1 = __float_as_uint(kr[tig + 4]);
                    asm volatile(
                        "mma.sync.aligned.m16n8k8.row.col.f32.tf32.tf32.f32 "
                        "{%0,%1,%2,%3}, {%4,%5,%6,%7}, {%8,%9}, {%0,%1,%2,%3};\n"
                        : "+f"(sc[j][0]), "+f"(sc[j][1]), "+f"(sc[j][2]), "+f"(sc[j][3])
                        : "r"(a0), "r"(a1), "r"(a2), "r"(a3), "r"(b0), "r"(b1));
                }
            }

            // ---- softmax (online), rows g and g+8 ----
            #pragma unroll
            for (int hh = 0; hh < 2; hh++) {
                int qq = qq0 + hh * 8;
                float mx = -INFINITY;
                #pragma unroll
                for (int j = 0; j < 8; j++) {
                    #pragma unroll
                    for (int e = 0; e < 2; e++) {
                        int kk = kt * 64 + j * 8 + 2 * tig + e;
                        float s = sc[j][hh * 2 + e] * scale - slope * (float)(qq - kk);
                        if (diag && kk > qq) s = -INFINITY;
                        sc[j][hh * 2 + e] = s;
                        mx = fmaxf(mx, s);
                    }
                }
                mx = fmaxf(mx, __shfl_xor_sync(0xffffffffu, mx, 1));
                mx = fmaxf(mx, __shfl_xor_sync(0xffffffffu, mx, 2));
                float mn = fmaxf(mrow[st][hh], mx);
                float corr = __expf(mrow[st][hh] - mn);
                mrow[st][hh] = mn;
                float rs = 0.f;
                #pragma unroll
                for (int j = 0; j < 8; j++) {
                    #pragma unroll
                    for (int e = 0; e < 2; e++) {
                        float pv = __expf(sc[j][hh * 2 + e] - mn);
                        sc[j][hh * 2 + e] = pv;
                        rs += pv;
                    }
                }
                rs += __shfl_xor_sync(0xffffffffu, rs, 1);
                rs += __shfl_xor_sync(0xffffffffu, rs, 2);
                lrow[st][hh] = lrow[st][hh] * corr + rs;
                #pragma unroll
                for (int j = 0; j < 8; j++) {
                    oacc[st][j][hh * 2 + 0] *= corr;
                    oacc[st][j][hh * 2 + 1] *= corr;
                }
            }

            // ---- write P (tf32 bits) to own-warp rows of sP ----
            #pragma unroll
            for (int hh = 0; hh < 2; hh++) {
                float* pr = sP + (w * 16 + g + hh * 8) * PLD;
                #pragma unroll
                for (int j = 0; j < 8; j++) {
                    float2 pv = make_float2(tf32f(sc[j][hh * 2 + 0]), tf32f(sc[j][hh * 2 + 1]));
                    *(float2*)(pr + j * 8 + 2 * tig) = pv;
                }
            }
            __syncwarp();  // sP rows warp-private

            // ---- PV: oacc += P @ V ----
            #pragma unroll
            for (int k8 = 0; k8 < 8; k8++) {
                uint32_t a0, a1, a2, a3;
                uint32_t addr = pa_lane + (uint32_t)(k8 * 8) * 4u;
                asm volatile("ldmatrix.sync.aligned.m8n8.x4.shared.b16 {%0,%1,%2,%3}, [%4];\n"
                             : "=r"(a0), "=r"(a1), "=r"(a2), "=r"(a3) : "r"(addr));
                const float* vp = sV + (k8 * 8 + tig) * VLD;
                #pragma unroll
                for (int j = 0; j < 8; j++) {
                    uint32_t b0 = __float_as_uint(vp[j * 8 + g]);
                    uint32_t b1 = __float_as_uint(vp[4 * VLD + j * 8 + g]);
                    asm volatile(
                        "mma.sync.aligned.m16n8k8.row.col.f32.tf32.tf32.f32 "
                        "{%0,%1,%2,%3}, {%4,%5,%6,%7}, {%8,%9}, {%0,%1,%2,%3};\n"
                        : "+f"(oacc[st][j][0]), "+f"(oacc[st][j][1]),
                          "+f"(oacc[st][j][2]), "+f"(oacc[st][j][3])
                        : "r"(a0), "r"(a1), "r"(a2), "r"(a3), "r"(b0), "r"(b1));
                }
            }
            __syncwarp();  // stream 1 P-write must not pass stream 0 P-reads
        }
        __syncthreads();  // all reads done before next kt overwrites tiles
    }

    // --- epilogue: combine streams, per-head LayerNorm over DH, store ---
    float lam = g_lambda;
    #pragma unroll
    for (int hh = 0; hh < 2; hh++) {
        float inv0 = 1.0f / lrow[0][hh];
        float inv1 = 1.0f / lrow[1][hh];
        float o[8][2];
        float s_ = 0.f;
        #pragma unroll
        for (int j = 0; j < 8; j++) {
            #pragma unroll
            for (int e = 0; e < 2; e++) {
                float val = oacc[0][j][hh * 2 + e] * inv0
                          - lam * (oacc[1][j][hh * 2 + e] * inv1);
                o[j][e] = val;
                s_ += val;
            }
        }
        s_ += __shfl_xor_sync(0xffffffffu, s_, 1);
        s_ += __shfl_xor_sync(0xffffffffu, s_, 2);
        float mu = s_ * (1.0f / 64.0f);
        float vs = 0.f;
        #pragma unroll
        for (int j = 0; j < 8; j++) {
            #pragma unroll
            for (int e = 0; e < 2; e++) { float d = o[j][e] - mu; vs += d * d; }
        }
        vs += __shfl_xor_sync(0xffffffffu, vs, 1);
        vs += __shfl_xor_sync(0xffffffffu, vs, 2);
        float r = rsqrtf(vs * (1.0f / 64.0f) + LN_EPS);

        size_t row = (size_t)b * SEQ + (size_t)(qrow0 + g + hh * 8);
        #pragma unroll
        for (int j = 0; j < 8; j++) {
            int col = h * DHEAD + j * 8 + 2 * tig;
            float wv0 = ln_w[h * DHEAD + j * 8 + 2 * tig];
            float wv1 = ln_w[h * DHEAD + j * 8 + 2 * tig + 1];
            float bv0 = ln_b[h * DHEAD + j * 8 + 2 * tig];
            float bv1 = ln_b[h * DHEAD + j * 8 + 2 * tig + 1];
            float2 res = make_float2((o[j][0] - mu) * r * wv0 + bv0,
                                     (o[j][1] - mu) * r * wv1 + bv1);
            *(float2*)(attn + row * DMODEL + col) = res;
        }
    }
}

// ---------------------------------------------------------------------------
// Launch
// ---------------------------------------------------------------------------
extern "C" void kernel_launch(void* const* d_in, const int* in_sizes, int n_in,
                              void* d_out, int out_size) {
    const float* inp = (const float*)d_in[0];
    const float* wq0 = (const float*)d_in[1];
    const float* wq1 = (const float*)d_in[2];
    const float* wk0 = (const float*)d_in[3];
    const float* wk1 = (const float*)d_in[4];
    const float* wv  = (const float*)d_in[5];
    const float* wo  = (const float*)d_in[6];
    const float* l0  = (const float*)d_in[7];
    const float* l1  = (const float*)d_in[8];
    const float* l2  = (const float*)d_in[9];
    const float* l3  = (const float*)d_in[10];
    const float* lnw = (const float*)d_in[11];
    const float* lnb = (const float*)d_in[12];
    float* out = (float*)d_out;

    float *q0, *q1, *k0, *k1, *v, *attn;
    cudaGetSymbolAddress((void**)&q0, g_q0);
    cudaGetSymbolAddress((void**)&q1, g_q1);
    cudaGetSymbolAddress((void**)&k0, g_k0);
    cudaGetSymbolAddress((void**)&k1, g_k1);
    cudaGetSymbolAddress((void**)&v,  g_v);
    cudaGetSymbolAddress((void**)&attn, g_attn);

    cudaFuncSetAttribute(gemm_tf32, cudaFuncAttributeMaxDynamicSharedMemorySize,
                         GEMM_SMEM_BYTES);
    cudaFuncSetAttribute(gemm_proj, cudaFuncAttributeMaxDynamicSharedMemorySize,
                         GEMM_SMEM_BYTES);
    cudaFuncSetAttribute(attn_tc_kernel, cudaFuncAttributeMaxDynamicSharedMemorySize,
                         ATTN2_SMEM_BYTES);

    lambda_kernel<<<1, 32>>>(l0, l1, l2, l3);

    ProjPtrs pp;
    pp.W[0] = wq0; pp.W[1] = wq1; pp.W[2] = wk0; pp.W[3] = wk1; pp.W[4] = wv;
    pp.O[0] = q0;  pp.O[1] = q1;  pp.O[2] = k0;  pp.O[3] = k1;  pp.O[4] = v;

    dim3 pgrid(DMODEL / 128, MTOT / 128, 5);   // (8, 32, 5)
    gemm_proj<<<pgrid, 256, GEMM_SMEM_BYTES>>>(inp, pp, MTOT, DMODEL, DMODEL);

    attn_tc_kernel<<<dim3(SEQ / 64, BATCH * NHEAD), 128, ATTN2_SMEM_BYTES>>>(
        q0, q1, k0, k1, v, lnw, lnb, attn);

    dim3 ggrid(DMODEL / 128, MTOT / 128);      // (8, 32)
    gemm_tf32<<<ggrid, 256, GEMM_SMEM_BYTES>>>(attn, wo, out, MTOT, DMODEL, DMODEL);
}